// round 16
// baseline (speedup 1.0000x reference)
#include <cuda_runtime.h>
#include <cuda_bf16.h>
#include <math.h>
#include <stdint.h>

// Problem dims (fixed by the dataset)
#define BD   4
#define LSEQ 4096
#define DM   1024
#define DH   2048
#define MROWS (BD * LSEQ)   // 16384
#define NCHK 64
#define LCHK 64             // NCHK*LCHK == LSEQ

static constexpr size_t SZ_D = (size_t)MROWS * DM;   // 16.78M
static constexpr size_t SZ_H = (size_t)MROWS * DH;   // 33.55M

// ---------------- scratch (no allocations allowed) ----------------
__device__ float g_x1 [SZ_D];
__device__ float g_h1 [SZ_H];   // dl pre-activation
__device__ float g_h2 [SZ_H];   // A_bar (emitted by A_t GEMM epilogue)
__device__ float g_h3 [SZ_H];   // B_x
__device__ float g_ssm[SZ_D];
__device__ float g_z  [SZ_D];
// scan carries: [BD][NCHK][DH]
__device__ float g_P [(size_t)BD * NCHK * DH];
__device__ float g_Q [(size_t)BD * NCHK * DH];

// bf16 hi/lo planes for activations
__device__ uint16_t gxh [SZ_D], gxl [SZ_D];
__device__ uint16_t gxch[SZ_D], gxcl[SZ_D];
__device__ uint16_t ghh [SZ_H], ghl [SZ_H];
__device__ uint16_t gsh [SZ_D], gsl [SZ_D];
__device__ uint16_t gzh [SZ_D], gzl [SZ_D];
// weights hi/lo
__device__ uint16_t gw1h[DM * DM], gw1l[DM * DM];
__device__ uint16_t gw2h[DM * DM], gw2l[DM * DM];
__device__ uint16_t gw3h[DM * DM], gw3l[DM * DM];
__device__ uint16_t gDwh[DM * DM], gDwl[DM * DM];
__device__ uint16_t gAwh[DH * DM], gAwl[DH * DM];
__device__ uint16_t gBwh[DH * DM], gBwl[DH * DM];
__device__ uint16_t gdlh[DH * DM], gdll[DH * DM];
__device__ uint16_t gCwh[DM * DH], gCwl[DM * DH];

__device__ __forceinline__ float siluf(float x) { return x / (1.0f + __expf(-x)); }
__device__ __forceinline__ float softplusf(float x) {
    return (x > 15.0f) ? x : __logf(1.0f + __expf(x));
}

__device__ __forceinline__ uint32_t smem_u32(const void* p) {
    uint32_t a;
    asm("{ .reg .u64 t; cvta.to.shared.u64 t, %1; cvt.u32.u64 %0, t; }" : "=r"(a) : "l"(p));
    return a;
}

#define CP_ASYNC16(s, g) \
    asm volatile("cp.async.cg.shared.global [%0], [%1], 16;" :: "r"(s), "l"(g) : "memory")
#define CP_COMMIT() asm volatile("cp.async.commit_group;" ::: "memory")
#define CP_WAIT1()  asm volatile("cp.async.wait_group 1;" ::: "memory")
#define CP_WAIT0()  asm volatile("cp.async.wait_group 0;" ::: "memory")

__device__ __forceinline__ void ldsm4(uint32_t* r, uint32_t addr) {
    asm volatile("ldmatrix.sync.aligned.m8n8.x4.shared.b16 {%0,%1,%2,%3}, [%4];"
                 : "=r"(r[0]), "=r"(r[1]), "=r"(r[2]), "=r"(r[3]) : "r"(addr));
}

__device__ __forceinline__ void mma_bf16(float* c, const uint32_t* a, const uint32_t* b) {
    asm volatile(
        "mma.sync.aligned.m16n8k16.row.col.f32.bf16.bf16.f32 "
        "{%0,%1,%2,%3}, {%4,%5,%6,%7}, {%8,%9}, {%0,%1,%2,%3};"
        : "+f"(c[0]), "+f"(c[1]), "+f"(c[2]), "+f"(c[3])
        : "r"(a[0]), "r"(a[1]), "r"(a[2]), "r"(a[3]), "r"(b[0]), "r"(b[1]));
}

__device__ __forceinline__ uint16_t bf16h(float x) {
    return __bfloat16_as_ushort(__float2bfloat16(x));
}
__device__ __forceinline__ float bf16f(uint16_t u) {
    return __bfloat162float(__ushort_as_bfloat16(u));
}
__device__ __forceinline__ void split4(const float* v, uint2& hp, uint2& lp) {
    uint16_t h0 = bf16h(v[0]), h1 = bf16h(v[1]), h2 = bf16h(v[2]), h3 = bf16h(v[3]);
    uint16_t l0 = bf16h(v[0] - bf16f(h0));
    uint16_t l1 = bf16h(v[1] - bf16f(h1));
    uint16_t l2 = bf16h(v[2] - bf16f(h2));
    uint16_t l3 = bf16h(v[3] - bf16f(h3));
    hp.x = ((uint32_t)h1 << 16) | h0; hp.y = ((uint32_t)h3 << 16) | h2;
    lp.x = ((uint32_t)l1 << 16) | l0; lp.y = ((uint32_t)l3 << 16) | l2;
}

// SW64 swizzle for 64B rows: XOR 16B-group index (bits 5:4) with row bits (9:7)>>3
__device__ __forceinline__ uint32_t sw64(uint32_t off) { return off ^ ((off >> 3) & 0x30); }

// ===================== bf16-split GEMM on mma.sync =====================
enum { EP_NONE = 0, EP_ACCUM = 1, EP_MUL_SILU = 2, EP_ADD_AUX = 3, EP_ABAR = 4 };

static constexpr int RS    = 64;           // SMEM row stride (bytes) — swizzled, no pad
static constexpr int PLANE = 128 * RS;     // 8192
static constexpr int STG   = 4 * PLANE;    // 32768 (Ahi|Alo|Bhi|Blo)
static constexpr int NSTG  = 3;
static constexpr int GEMM_SMEM = NSTG * STG;   // 98304 -> 2 CTAs/SM

template <int EP, bool EMIT>
__global__ __launch_bounds__(256, 2) void gemm_mma(
    const uint16_t* __restrict__ Ah, const uint16_t* __restrict__ Al,
    const uint16_t* __restrict__ Bh, const uint16_t* __restrict__ Bl,
    const float* __restrict__ bias, const float* __restrict__ aux,
    float* __restrict__ C, uint16_t* __restrict__ Ch, uint16_t* __restrict__ Cl,
    int M, int N, int K)
{
    extern __shared__ char smem[];
    const uint32_t sb = smem_u32(smem);
    const int tid = threadIdx.x;
    const int wid = tid >> 5, l = tid & 31;
    const int warp_m = (wid >> 2) * 64;
    const int warp_n = (wid & 3) * 32;
    const int mtile = blockIdx.y, ntile = blockIdx.x;
    const int nch = K >> 5;

    const int ld_row = tid >> 2;
    const int ld_ch  = tid & 3;
    const size_t arow = (size_t)mtile * 128;
    const size_t brow = (size_t)ntile * 128;
    const uint32_t woff = sw64((uint32_t)(ld_row * RS + ld_ch * 16));

    auto load_stage = [&](int s, int c) {
        const uint32_t st = sb + s * STG;
        const size_t kc = (size_t)c << 5;
        const uint16_t* gp0 = Ah + (arow + ld_row) * (size_t)K + kc + ld_ch * 8;
        const uint16_t* gp1 = Al + (arow + ld_row) * (size_t)K + kc + ld_ch * 8;
        const uint16_t* gp2 = Bh + (brow + ld_row) * (size_t)K + kc + ld_ch * 8;
        const uint16_t* gp3 = Bl + (brow + ld_row) * (size_t)K + kc + ld_ch * 8;
        const uint32_t s0 = st + woff;
        const size_t stp = (size_t)64 * K;
        CP_ASYNC16(s0,                  gp0);
        CP_ASYNC16(s0 + 4096,           gp0 + stp);   // +64 rows
        CP_ASYNC16(s0 + PLANE,          gp1);
        CP_ASYNC16(s0 + PLANE + 4096,   gp1 + stp);
        CP_ASYNC16(s0 + 2*PLANE,        gp2);
        CP_ASYNC16(s0 + 2*PLANE + 4096, gp2 + stp);
        CP_ASYNC16(s0 + 3*PLANE,        gp3);
        CP_ASYNC16(s0 + 3*PLANE + 4096, gp3 + stp);
    };

    const int arow_l = warp_m + (l & 7) + ((l >> 3) & 1) * 8;
    const uint32_t aL = sb + sw64((uint32_t)(arow_l * RS + (l >> 4) * 16));
    const int brow_l = warp_n + (l & 7) + (l >> 4) * 8;
    const uint32_t bL = sb + 2 * PLANE + sw64((uint32_t)(brow_l * RS + ((l >> 3) & 1) * 16));

    float acc[4][4][4];
#pragma unroll
    for (int i = 0; i < 4; i++)
#pragma unroll
        for (int j = 0; j < 4; j++)
#pragma unroll
            for (int e = 0; e < 4; e++) acc[i][j][e] = 0.0f;

    load_stage(0, 0); CP_COMMIT();
    load_stage(1, 1); CP_COMMIT();

    int sidx = 0;   // stage of chunk c
    for (int c = 0; c < nch; ++c) {
        if (c + 1 < nch) CP_WAIT1(); else CP_WAIT0();
        __syncthreads();            // stage c visible CTA-wide; stage (c-1) reads done
        if (c + 2 < nch) {
            int s2 = sidx + 2; if (s2 >= NSTG) s2 -= NSTG;
            load_stage(s2, c + 2);  // overwrites buffer of chunk c-1
            CP_COMMIT();
        }

        const uint32_t so = (uint32_t)(sidx * STG);
#pragma unroll
        for (int ks = 0; ks < 2; ++ks) {
            const uint32_t ao = (aL + so) ^ (ks << 5);
            const uint32_t bo = (bL + so) ^ (ks << 5);
            uint32_t afh[4][4], afl[4][4], bfh[4][2], bfl[4][2];
#pragma unroll
            for (int mt = 0; mt < 4; ++mt) {
                ldsm4(afh[mt], ao + mt * 16 * RS);
                ldsm4(afl[mt], ao + PLANE + mt * 16 * RS);
            }
#pragma unroll
            for (int j = 0; j < 2; ++j) {
                uint32_t t[4];
                ldsm4(t, bo + j * 16 * RS);
                bfh[2*j][0] = t[0]; bfh[2*j][1] = t[1];
                bfh[2*j+1][0] = t[2]; bfh[2*j+1][1] = t[3];
                ldsm4(t, bo + PLANE + j * 16 * RS);
                bfl[2*j][0] = t[0]; bfl[2*j][1] = t[1];
                bfl[2*j+1][0] = t[2]; bfl[2*j+1][1] = t[3];
            }
#pragma unroll
            for (int mt = 0; mt < 4; ++mt)
#pragma unroll
                for (int nt = 0; nt < 4; ++nt) {
                    mma_bf16(acc[mt][nt], afh[mt], bfh[nt]);
                    mma_bf16(acc[mt][nt], afh[mt], bfl[nt]);
                    mma_bf16(acc[mt][nt], afl[mt], bfh[nt]);
                }
        }
        if (++sidx == NSTG) sidx = 0;
    }

    // epilogue
    const int mrow0 = mtile * 128 + warp_m + (l >> 2);
    const int coln0 = ntile * 128 + warp_n + (l & 3) * 2;
#pragma unroll
    for (int mt = 0; mt < 4; ++mt) {
#pragma unroll
        for (int nt = 0; nt < 4; ++nt) {
            const int col = coln0 + nt * 8;
#pragma unroll
            for (int h = 0; h < 2; ++h) {
                const int row = mrow0 + mt * 16 + h * 8;
                float v0 = acc[mt][nt][h * 2 + 0];
                float v1 = acc[mt][nt][h * 2 + 1];
                if (bias) { v0 += bias[col]; v1 += bias[col + 1]; }
                const size_t idx = (size_t)row * N + col;
                if (EP == EP_ACCUM) {
                    float2 cv = *reinterpret_cast<const float2*>(&C[idx]);
                    v0 += cv.x; v1 += cv.y;
                } else if (EP == EP_MUL_SILU) {
                    float2 av = *reinterpret_cast<const float2*>(&aux[idx]);
                    v0 = av.x * siluf(v0); v1 = av.y * siluf(v1);
                } else if (EP == EP_ADD_AUX) {
                    float2 av = *reinterpret_cast<const float2*>(&aux[idx]);
                    v0 = av.x + v0; v1 = av.y + v1;
                } else if (EP == EP_ABAR) {
                    // aux = dl pre-activation; acc+bias = A_t; emit exp(-softplus(dl)*A_t)
                    float2 av = *reinterpret_cast<const float2*>(&aux[idx]);
                    v0 = __expf(-softplusf(av.x) * v0);
                    v1 = __expf(-softplusf(av.y) * v1);
                }
                float2 ov; ov.x = v0; ov.y = v1;
                *reinterpret_cast<float2*>(&C[idx]) = ov;
                if (EMIT) {
                    uint16_t h0 = bf16h(v0), h1 = bf16h(v1);
                    uint16_t l0 = bf16h(v0 - bf16f(h0)), l1 = bf16h(v1 - bf16f(h1));
                    *reinterpret_cast<uint32_t*>(&Ch[idx]) = ((uint32_t)h1 << 16) | h0;
                    *reinterpret_cast<uint32_t*>(&Cl[idx]) = ((uint32_t)l1 << 16) | l0;
                }
            }
        }
    }
}

// -------------- tiny probe kernels (index alignment for ncu capture) --------
__global__ void probe_a(float* p) { if (threadIdx.x == 0 && blockIdx.x == 0) p[0] = 0.0f; }
__global__ void probe_b(float* p) { if (threadIdx.x == 0 && blockIdx.x == 0) p[0] = 0.0f; }

// -------------- batched conversions: x + 8 weights, one launch --------------
struct CvtPack9 {
    const float* src[9];
    uint16_t* hi[9];
    uint16_t* lo[9];
};
// region 0: x (2^22 float4); regions 1-4: DM*DM (2^18 each); 5-8: DH*DM (2^19 each)
static constexpr unsigned CVT9_N4 = (1u << 22) + (4u << 18) + (4u << 19);   // 7340032

__global__ void cvt_split9(CvtPack9 p)
{
    unsigned i = blockIdx.x * blockDim.x + threadIdx.x;
    if (i >= CVT9_N4) return;
    unsigned r, off;
    if (i < (1u << 22)) { r = 0; off = i; }
    else {
        unsigned j = i - (1u << 22);
        if (j < (4u << 18)) { r = 1 + (j >> 18); off = j & ((1u << 18) - 1); }
        else { unsigned k = j - (4u << 18); r = 5 + (k >> 19); off = k & ((1u << 19) - 1); }
    }
    float4 v = reinterpret_cast<const float4*>(p.src[r])[off];
    uint2 hp, lp; split4(&v.x, hp, lp);
    reinterpret_cast<uint2*>(p.hi[r])[off] = hp;
    reinterpret_cast<uint2*>(p.lo[r])[off] = lp;
}

// -------------- depthwise conv1d (k=3, pad=1) + bias + SiLU (vec4) ----------
__global__ void conv_silu_bf16_v4(const float* __restrict__ x,
                                  const float* __restrict__ w, const float* __restrict__ b,
                                  uint16_t* __restrict__ yh, uint16_t* __restrict__ yl)
{
    size_t i4 = (size_t)blockIdx.x * blockDim.x + threadIdx.x;
    const size_t n4 = SZ_D / 4;
    if (i4 >= n4) return;
    const size_t idx = i4 * 4;
    const int d = (int)(idx % DM);
    const int t = (int)((idx / DM) % LSEQ);

    float4 xc = *reinterpret_cast<const float4*>(x + idx);
    float4 xm = make_float4(0.f, 0.f, 0.f, 0.f);
    float4 xp = make_float4(0.f, 0.f, 0.f, 0.f);
    if (t > 0)        xm = *reinterpret_cast<const float4*>(x + idx - DM);
    if (t < LSEQ - 1) xp = *reinterpret_cast<const float4*>(x + idx + DM);
    float4 wA = *reinterpret_cast<const float4*>(w + (size_t)d * 3);
    float4 wB = *reinterpret_cast<const float4*>(w + (size_t)d * 3 + 4);
    float4 wC = *reinterpret_cast<const float4*>(w + (size_t)d * 3 + 8);
    const float wf[12] = {wA.x, wA.y, wA.z, wA.w, wB.x, wB.y, wB.z, wB.w,
                          wC.x, wC.y, wC.z, wC.w};
    float4 bb = *reinterpret_cast<const float4*>(b + d);
    const float xmv[4] = {xm.x, xm.y, xm.z, xm.w};
    const float xcv[4] = {xc.x, xc.y, xc.z, xc.w};
    const float xpv[4] = {xp.x, xp.y, xp.z, xp.w};
    const float bv[4]  = {bb.x, bb.y, bb.z, bb.w};
    float out[4];
#pragma unroll
    for (int k = 0; k < 4; ++k) {
        float s = bv[k];
        s = fmaf(wf[k * 3 + 0], xmv[k], s);
        s = fmaf(wf[k * 3 + 1], xcv[k], s);
        s = fmaf(wf[k * 3 + 2], xpv[k], s);
        out[k] = siluf(s);
    }
    uint2 hp, lp; split4(out, hp, lp);
    reinterpret_cast<uint2*>(yh)[i4] = hp;
    reinterpret_cast<uint2*>(yl)[i4] = lp;
}

// -------------- chunked scan over precomputed A_bar (8 channels/thread) -----
__global__ void scan_p1_v8(const float* __restrict__ AB, const float* __restrict__ BX,
                           float* __restrict__ P, float* __restrict__ Q)
{
    unsigned i = blockIdx.x * blockDim.x + threadIdx.x;
    const unsigned tot8 = (unsigned)(BD * NCHK * DH / 8);
    if (i >= tot8) return;
    const unsigned idx = i * 8;
    const int hc = (int)(idx % DH);
    const int c  = (int)((idx / DH) % NCHK);
    const int b  = (int)(idx / (DH * NCHK));
    const size_t base = ((size_t)b * LSEQ + (size_t)c * LCHK) * DH + hc;
    float a[8] = {1,1,1,1,1,1,1,1}, q[8] = {0,0,0,0,0,0,0,0};
#pragma unroll 2
    for (int t = 0; t < LCHK; ++t) {
        const size_t off = base + (size_t)t * DH;
        float4 ab0 = *reinterpret_cast<const float4*>(AB + off);
        float4 ab1 = *reinterpret_cast<const float4*>(AB + off + 4);
        float4 bx0 = *reinterpret_cast<const float4*>(BX + off);
        float4 bx1 = *reinterpret_cast<const float4*>(BX + off + 4);
        const float abv[8] = {ab0.x, ab0.y, ab0.z, ab0.w, ab1.x, ab1.y, ab1.z, ab1.w};
        const float bxv[8] = {bx0.x, bx0.y, bx0.z, bx0.w, bx1.x, bx1.y, bx1.z, bx1.w};
#pragma unroll
        for (int k = 0; k < 8; ++k) {
            a[k] *= abv[k];
            q[k] = fmaf(bxv[k], a[k], q[k]);
        }
    }
    const size_t ci = ((size_t)b * NCHK + c) * DH + hc;
    *reinterpret_cast<float4*>(P + ci)     = make_float4(a[0], a[1], a[2], a[3]);
    *reinterpret_cast<float4*>(P + ci + 4) = make_float4(a[4], a[5], a[6], a[7]);
    *reinterpret_cast<float4*>(Q + ci)     = make_float4(q[0], q[1], q[2], q[3]);
    *reinterpret_cast<float4*>(Q + ci + 4) = make_float4(q[4], q[5], q[6], q[7]);
}

__global__ void scan_p2_v4(float* __restrict__ P, float* __restrict__ Q)
{
    unsigned i = blockIdx.x * blockDim.x + threadIdx.x;
    const unsigned tot4 = (unsigned)(BD * DH / 4);
    if (i >= tot4) return;
    const unsigned idx = i * 4;
    const int b  = (int)(idx / DH);
    const int hc = (int)(idx % DH);
    float a[4] = {1.f, 1.f, 1.f, 1.f}, s[4] = {0.f, 0.f, 0.f, 0.f};
    for (int c = 0; c < NCHK; ++c) {
        const size_t ci = ((size_t)b * NCHK + c) * DH + hc;
        float4 tp = *reinterpret_cast<float4*>(P + ci);
        float4 tq = *reinterpret_cast<float4*>(Q + ci);
        *reinterpret_cast<float4*>(P + ci) = make_float4(a[0], a[1], a[2], a[3]);
        *reinterpret_cast<float4*>(Q + ci) = make_float4(s[0], s[1], s[2], s[3]);
        const float tpv[4] = {tp.x, tp.y, tp.z, tp.w};
        const float tqv[4] = {tq.x, tq.y, tq.z, tq.w};
#pragma unroll
        for (int k = 0; k < 4; ++k) {
            s[k] = fmaf(a[k], tqv[k], s[k]);
            a[k] *= tpv[k];
        }
    }
}

__global__ void scan_p3_v8(const float* __restrict__ AB, const float* __restrict__ BX,
                           const float* __restrict__ Ain, const float* __restrict__ Sin,
                           uint16_t* __restrict__ hh, uint16_t* __restrict__ hl)
{
    unsigned i = blockIdx.x * blockDim.x + threadIdx.x;
    const unsigned tot8 = (unsigned)(BD * NCHK * DH / 8);
    if (i >= tot8) return;
    const unsigned idx = i * 8;
    const int hc = (int)(idx % DH);
    const int c  = (int)((idx / DH) % NCHK);
    const int b  = (int)(idx / (DH * NCHK));
    const size_t base = ((size_t)b * LSEQ + (size_t)c * LCHK) * DH + hc;
    const size_t ci = ((size_t)b * NCHK + c) * DH + hc;
    float4 a0 = *reinterpret_cast<const float4*>(Ain + ci);
    float4 a1 = *reinterpret_cast<const float4*>(Ain + ci + 4);
    float4 s0 = *reinterpret_cast<const float4*>(Sin + ci);
    float4 s1 = *reinterpret_cast<const float4*>(Sin + ci + 4);
    float a[8] = {a0.x, a0.y, a0.z, a0.w, a1.x, a1.y, a1.z, a1.w};
    float s[8] = {s0.x, s0.y, s0.z, s0.w, s1.x, s1.y, s1.z, s1.w};
#pragma unroll 2
    for (int t = 0; t < LCHK; ++t) {
        const size_t off = base + (size_t)t * DH;
        float4 ab0 = *reinterpret_cast<const float4*>(AB + off);
        float4 ab1 = *reinterpret_cast<const float4*>(AB + off + 4);
        float4 bx0 = *reinterpret_cast<const float4*>(BX + off);
        float4 bx1 = *reinterpret_cast<const float4*>(BX + off + 4);
        const float abv[8] = {ab0.x, ab0.y, ab0.z, ab0.w, ab1.x, ab1.y, ab1.z, ab1.w};
        const float bxv[8] = {bx0.x, bx0.y, bx0.z, bx0.w, bx1.x, bx1.y, bx1.z, bx1.w};
#pragma unroll
        for (int k = 0; k < 8; ++k) {
            a[k] *= abv[k];
            s[k] = fmaf(bxv[k], a[k], s[k]);
        }
        uint2 hp0, lp0, hp1, lp1;
        split4(s,     hp0, lp0);
        split4(s + 4, hp1, lp1);
        reinterpret_cast<uint2*>(hh)[off / 4]     = hp0;
        reinterpret_cast<uint2*>(hh)[off / 4 + 1] = hp1;
        reinterpret_cast<uint2*>(hl)[off / 4]     = lp0;
        reinterpret_cast<uint2*>(hl)[off / 4 + 1] = lp1;
    }
}

// ---------------------------------------------------------------------------
extern "C" void kernel_launch(void* const* d_in, const int* in_sizes, int n_in,
                              void* d_out, int out_size)
{
    const float* x      = (const float*)d_in[0];
    const float* w1     = (const float*)d_in[1];
    const float* w2     = (const float*)d_in[2];
    const float* w3     = (const float*)d_in[3];
    const float* conv_w = (const float*)d_in[4];
    const float* conv_b = (const float*)d_in[5];
    const float* A_w    = (const float*)d_in[6];
    const float* A_b    = (const float*)d_in[7];
    const float* B_w    = (const float*)d_in[8];
    const float* B_b    = (const float*)d_in[9];
    const float* C_w    = (const float*)d_in[10];
    const float* C_b    = (const float*)d_in[11];
    const float* D_w    = (const float*)d_in[12];
    const float* D_b    = (const float*)d_in[13];
    const float* dl_w   = (const float*)d_in[14];
    const float* dl_b   = (const float*)d_in[15];
    float* out = (float*)d_out;

    float *x1, *h1, *h2, *h3, *ssm, *z, *Pc, *Qc;
    uint16_t *xh, *xl, *xch, *xcl, *hh, *hl, *sh, *sl, *zh, *zl;
    uint16_t *w1h, *w1l, *w2h, *w2l, *w3h, *w3l, *Dwh, *Dwl;
    uint16_t *Awh, *Awl, *Bwh, *Bwl, *dlh, *dll, *Cwh, *Cwl;
    cudaGetSymbolAddress((void**)&x1,  g_x1);
    cudaGetSymbolAddress((void**)&h1,  g_h1);
    cudaGetSymbolAddress((void**)&h2,  g_h2);
    cudaGetSymbolAddress((void**)&h3,  g_h3);
    cudaGetSymbolAddress((void**)&ssm, g_ssm);
    cudaGetSymbolAddress((void**)&z,   g_z);
    cudaGetSymbolAddress((void**)&Pc,  g_P);
    cudaGetSymbolAddress((void**)&Qc,  g_Q);
    cudaGetSymbolAddress((void**)&xh,  gxh);  cudaGetSymbolAddress((void**)&xl,  gxl);
    cudaGetSymbolAddress((void**)&xch, gxch); cudaGetSymbolAddress((void**)&xcl, gxcl);
    cudaGetSymbolAddress((void**)&hh,  ghh);  cudaGetSymbolAddress((void**)&hl,  ghl);
    cudaGetSymbolAddress((void**)&sh,  gsh);  cudaGetSymbolAddress((void**)&sl,  gsl);
    cudaGetSymbolAddress((void**)&zh,  gzh);  cudaGetSymbolAddress((void**)&zl,  gzl);
    cudaGetSymbolAddress((void**)&w1h, gw1h); cudaGetSymbolAddress((void**)&w1l, gw1l);
    cudaGetSymbolAddress((void**)&w2h, gw2h); cudaGetSymbolAddress((void**)&w2l, gw2l);
    cudaGetSymbolAddress((void**)&w3h, gw3h); cudaGetSymbolAddress((void**)&w3l, gw3l);
    cudaGetSymbolAddress((void**)&Dwh, gDwh); cudaGetSymbolAddress((void**)&Dwl, gDwl);
    cudaGetSymbolAddress((void**)&Awh, gAwh); cudaGetSymbolAddress((void**)&Awl, gAwl);
    cudaGetSymbolAddress((void**)&Bwh, gBwh); cudaGetSymbolAddress((void**)&Bwl, gBwl);
    cudaGetSymbolAddress((void**)&dlh, gdlh); cudaGetSymbolAddress((void**)&dll, gdll);
    cudaGetSymbolAddress((void**)&Cwh, gCwh); cudaGetSymbolAddress((void**)&Cwl, gCwl);

    cudaFuncSetAttribute(gemm_mma<EP_NONE, false>,    cudaFuncAttributeMaxDynamicSharedMemorySize, GEMM_SMEM);
    cudaFuncSetAttribute(gemm_mma<EP_ABAR, false>,    cudaFuncAttributeMaxDynamicSharedMemorySize, GEMM_SMEM);
    cudaFuncSetAttribute(gemm_mma<EP_ACCUM, true>,    cudaFuncAttributeMaxDynamicSharedMemorySize, GEMM_SMEM);
    cudaFuncSetAttribute(gemm_mma<EP_MUL_SILU, true>, cudaFuncAttributeMaxDynamicSharedMemorySize, GEMM_SMEM);
    cudaFuncSetAttribute(gemm_mma<EP_ADD_AUX, false>, cudaFuncAttributeMaxDynamicSharedMemorySize, GEMM_SMEM);

    const dim3 blk(256);
    const dim3 gD(DM / 128, MROWS / 128);   // N=1024 -> (8,128)
    const dim3 gH(DH / 128, MROWS / 128);   // N=2048 -> (16,128)

    // 0,1) probes (index alignment: puts gemm at launch index 3 for ncu)
    probe_a<<<1, 32>>>(Pc);
    probe_b<<<1, 32>>>(Qc);
    // 2) all conversions (x + 8 weights) in one launch
    {
        CvtPack9 p;
        p.src[0] = x;    p.hi[0] = xh;  p.lo[0] = xl;
        p.src[1] = w1;   p.hi[1] = w1h; p.lo[1] = w1l;
        p.src[2] = w2;   p.hi[2] = w2h; p.lo[2] = w2l;
        p.src[3] = w3;   p.hi[3] = w3h; p.lo[3] = w3l;
        p.src[4] = D_w;  p.hi[4] = Dwh; p.lo[4] = Dwl;
        p.src[5] = A_w;  p.hi[5] = Awh; p.lo[5] = Awl;
        p.src[6] = B_w;  p.hi[6] = Bwh; p.lo[6] = Bwl;
        p.src[7] = dl_w; p.hi[7] = dlh; p.lo[7] = dll;
        p.src[8] = C_w;  p.hi[8] = Cwh; p.lo[8] = Cwl;
        cvt_split9<<<(CVT9_N4 + 255) / 256, 256>>>(p);
    }
    // 3) x1 = x @ w1^T   <-- ncu capture target (launch index 3)
    gemm_mma<EP_NONE, false><<<gD, blk, GEMM_SMEM>>>(xh, xl, w1h, w1l, nullptr, nullptr,
                                                     x1, nullptr, nullptr, MROWS, DM, DM);
    // 4) xc = silu(conv(x1)+b) -> bf16 planes
    {
        size_t n4 = SZ_D / 4;
        conv_silu_bf16_v4<<<(unsigned)((n4 + 255) / 256), 256>>>(x1, conv_w, conv_b, xch, xcl);
    }
    // 5) dl GEMM -> h1 (pre-activation)
    gemm_mma<EP_NONE, false><<<gH, blk, GEMM_SMEM>>>(xch, xcl, dlh, dll, dl_b, nullptr,
                                                     h1, nullptr, nullptr, MROWS, DH, DM);
    // 6) A_t GEMM with fused A_bar epilogue -> h2 = exp(-softplus(h1)*(acc+A_b))
    gemm_mma<EP_ABAR, false><<<gH, blk, GEMM_SMEM>>>(xch, xcl, Awh, Awl, A_b, h1,
                                                     h2, nullptr, nullptr, MROWS, DH, DM);
    // 7) B_x GEMM -> h3
    gemm_mma<EP_NONE, false><<<gH, blk, GEMM_SMEM>>>(xch, xcl, Bwh, Bwl, B_b, nullptr,
                                                     h3, nullptr, nullptr, MROWS, DH, DM);
    // 8) ssm = xc @ D_w^T + D_b
    gemm_mma<EP_NONE, false><<<gD, blk, GEMM_SMEM>>>(xch, xcl, Dwh, Dwl, D_b, nullptr,
                                                     ssm, nullptr, nullptr, MROWS, DM, DM);
    // 9-11) chunked scan over (h2 = A_bar, h3 = B_x) -> h bf16 planes
    {
        const unsigned tot8 = (unsigned)(BD * NCHK * DH / 8);
        scan_p1_v8<<<(tot8 + 255) / 256, 256>>>(h2, h3, Pc, Qc);
        scan_p2_v4<<<((unsigned)(BD * DH / 4) + 255) / 256, 256>>>(Pc, Qc);
        scan_p3_v8<<<(tot8 + 255) / 256, 256>>>(h2, h3, Pc, Qc, hh, hl);
    }
    // 12) ssm += h @ C_w^T + C_b   (emit ssm bf16 planes)
    gemm_mma<EP_ACCUM, true><<<gD, blk, GEMM_SMEM>>>(hh, hl, Cwh, Cwl, C_b, nullptr,
                                                     ssm, sh, sl, MROWS, DM, DH);
    // 13) z = ssm * silu(ssm @ w2^T)  (emit z bf16 planes)
    gemm_mma<EP_MUL_SILU, true><<<gD, blk, GEMM_SMEM>>>(sh, sl, w2h, w2l, nullptr, ssm,
                                                        z, zh, zl, MROWS, DM, DM);
    // 14) out = ssm + z @ w3^T
    gemm_mma<EP_ADD_AUX, false><<<gD, blk, GEMM_SMEM>>>(zh, zl, w3h, w3l, nullptr, ssm,
                                                        out, nullptr, nullptr, MROWS, DM, DM);
}